// round 3
// baseline (speedup 1.0000x reference)
#include <cuda_runtime.h>

namespace {
constexpr int B_ = 4, H_ = 160, W_ = 160, D_ = 160;
constexpr int SX = D_;            // x stride
constexpr int SY = W_ * D_;       // y stride
constexpr int SB = H_ * W_ * D_;  // batch stride

// Tile / region geometry
constexpr int TY = 16, TX = 10, TZ = 32;
constexpr int HLO = 5;                          // low halo (high halo = 6)
constexpr int RY = TY + 11, RX = TX + 11, RZ = TZ + 11;  // 27, 21, 43
constexpr int REG = RY * RX * RZ;               // 24381 floats = 97.5 KB
constexpr int NTY = H_ / TY, NTX = W_ / TX, NTZ = D_ / TZ;  // 10,16,5
constexpr int NBLK = B_ * NTY * NTX * NTZ;      // 3200
constexpr int TPB = 512;

__device__ __forceinline__ float wcomb(float va, float vb, float vc, float vd,
                                       float ve, float vf, float vg, float vh,
                                       float ddx, float ddy, float ddz) {
    float ex = 1.0f - ddx, ey = 1.0f - ddy, ez = 1.0f - ddz;
    float s0 = fmaf(ddx, fmaf(ddy, va, ey * vb), ex * fmaf(ddy, vc, ey * vd));
    float s1 = fmaf(ddx, fmaf(ddy, ve, ey * vf), ex * fmaf(ddy, vg, ey * vh));
    return fmaf(ddz, s0, ez * s1);
}
}  // namespace

__global__ void __launch_bounds__(TPB)
dense3d_tile_kernel(const float* __restrict__ im,
                    const float* __restrict__ flow,
                    float* __restrict__ out) {
    extern __shared__ float sreg[];

    // Decode tile
    int bi = blockIdx.x;
    int tzi = bi % NTZ; bi /= NTZ;
    int txi = bi % NTX; bi /= NTX;
    int tyi = bi % NTY;
    int b   = bi / NTY;
    int ty0 = tyi * TY, tx0 = txi * TX, tz0 = tzi * TZ;
    int oy = ty0 - HLO, ox = tx0 - HLO, oz = tz0 - HLO;
    const float* imb = im + b * SB;

    // Phase 1: cooperatively stage haloed region (OOB cells skipped; never read)
    for (int i = threadIdx.x; i < REG; i += TPB) {
        int rz = i % RZ;
        int t = i / RZ;
        int rx = t % RX;
        int ry = t / RX;
        int gy = oy + ry, gx = ox + rx, gz = oz + rz;
        if ((unsigned)gy < (unsigned)H_ && (unsigned)gx < (unsigned)W_ &&
            (unsigned)gz < (unsigned)D_) {
            sreg[i] = __ldg(imb + gy * SY + gx * SX + gz);
        }
    }
    __syncthreads();

    // Phase 2: gather. Lane = z within tile (TZ == 32), warp per z-line.
    int lane = threadIdx.x & 31;
    int w = threadIdx.x >> 5;  // 16 warps

    for (int l = w; l < TY * TX; l += (TPB / 32)) {
        int tyv = l / TX, txv = l % TX;
        int gy = ty0 + tyv, gx = tx0 + txv, gz = tz0 + lane;
        int v = b * SB + gy * SY + gx * SX + gz;

        const float* fp = flow + (size_t)v * 3;
        float dyv = __ldg(fp + 0);  // flow[...,0] -> dy (H axis)
        float dxv = __ldg(fp + 1);  // flow[...,1] -> dx (W axis)
        float dzv = __ldg(fp + 2);  // flow[...,2] -> dz (D axis)

        float xf = dxv + (float)gx;
        float yf = dyv + (float)gy;
        float zf = dzv + (float)gz;

        // Reference-exact floor + clip
        int x0 = (int)floorf(xf);
        int y0 = (int)floorf(yf);
        int z0 = (int)floorf(zf);
        int x1 = min(max(x0 + 1, 0), W_ - 1);
        int y1 = min(max(y0 + 1, 0), H_ - 1);
        int z1 = min(max(z0 + 1, 0), D_ - 1);
        x0 = min(max(x0, 0), W_ - 1);
        y0 = min(max(y0, 0), H_ - 1);
        z0 = min(max(z0, 0), D_ - 1);

        float ddx = (float)x1 - xf;
        float ddy = (float)y1 - yf;
        float ddz = (float)z1 - zf;

        int x0r = x0 - ox, x1r = x1 - ox;
        int y0r = y0 - oy, y1r = y1 - oy;
        int z0r = z0 - oz, z1r = z1 - oz;

        float res;
        if (x0r >= 0 && x1r < RX && y0r >= 0 && y1r < RY &&
            z0r >= 0 && z1r < RZ) {
            const float* r00 = sreg + (y0r * RX + x0r) * RZ;
            const float* r10 = sreg + (y1r * RX + x0r) * RZ;
            const float* r01 = sreg + (y0r * RX + x1r) * RZ;
            const float* r11 = sreg + (y1r * RX + x1r) * RZ;
            float va = r00[z0r], vb = r10[z0r], vc = r01[z0r], vd = r11[z0r];
            float ve = r00[z1r], vf = r10[z1r], vg = r01[z1r], vh = r11[z1r];
            res = wcomb(va, vb, vc, vd, ve, vf, vg, vh, ddx, ddy, ddz);
        } else {
            // Rare exact fallback: gather from global
            const float* p00 = imb + y0 * SY + x0 * SX;
            const float* p10 = imb + y1 * SY + x0 * SX;
            const float* p01 = imb + y0 * SY + x1 * SX;
            const float* p11 = imb + y1 * SY + x1 * SX;
            float va = __ldg(p00 + z0), vb = __ldg(p10 + z0);
            float vc = __ldg(p01 + z0), vd = __ldg(p11 + z0);
            float ve = __ldg(p00 + z1), vf = __ldg(p10 + z1);
            float vg = __ldg(p01 + z1), vh = __ldg(p11 + z1);
            res = wcomb(va, vb, vc, vd, ve, vf, vg, vh, ddx, ddy, ddz);
        }
        out[v] = res;
    }
}

extern "C" void kernel_launch(void* const* d_in, const int* in_sizes, int n_in,
                              void* d_out, int out_size) {
    const float* im = (const float*)d_in[0];    // image [4,160,160,160,1]
    const float* flow = (const float*)d_in[1];  // flow  [4,160,160,160,3]
    float* out = (float*)d_out;

    static bool attr_set = false;  // idempotent attribute opt-in (not a guard on work)
    if (!attr_set) {
        cudaFuncSetAttribute(dense3d_tile_kernel,
                             cudaFuncAttributeMaxDynamicSharedMemorySize,
                             REG * (int)sizeof(float));
        attr_set = true;
    }
    dense3d_tile_kernel<<<NBLK, TPB, REG * sizeof(float)>>>(im, flow, out);
}

// round 4
// speedup vs baseline: 1.3856x; 1.3856x over previous
#include <cuda_runtime.h>

namespace {
constexpr int B_ = 4, H_ = 160, W_ = 160, D_ = 160;
constexpr int SX = D_;            // x stride
constexpr int SY = W_ * D_;       // y stride
constexpr int SB = H_ * W_ * D_;  // batch stride

// Tile / region geometry: halo lo=4, hi=5 (region dim = tile + 9)
constexpr int TY = 16, TX = 8, TZ = 32;
constexpr int HLO = 4;
constexpr int RY = TY + 9, RX = TX + 9, RZ = TZ + 9;  // 25, 17, 41
constexpr int REG = RY * RX * RZ;                      // 17425 floats = 69.7 KB
constexpr int NROWS = RY * RX;                         // 425
constexpr int SXY = RX * RZ;                           // 697
constexpr int NTY = H_ / TY, NTX = W_ / TX, NTZ = D_ / TZ;  // 10, 20, 5
constexpr int NBLK = B_ * NTY * NTX * NTZ;             // 4000
constexpr int TPB = 512;
constexpr int NWARP = TPB / 32;                        // 16
constexpr int LINES = TY * TX;                         // 128 -> 8 per warp

__device__ __forceinline__ float wcomb(float va, float vb, float vc, float vd,
                                       float ve, float vf, float vg, float vh,
                                       float ddx, float ddy, float ddz) {
    float ex = 1.0f - ddx, ey = 1.0f - ddy, ez = 1.0f - ddz;
    float s0 = fmaf(ddx, fmaf(ddy, va, ey * vb), ex * fmaf(ddy, vc, ey * vd));
    float s1 = fmaf(ddx, fmaf(ddy, ve, ey * vf), ex * fmaf(ddy, vg, ey * vh));
    return fmaf(ddz, s0, ez * s1);
}
}  // namespace

__global__ void __launch_bounds__(TPB)
dense3d_tile_kernel(const float* __restrict__ im,
                    const float* __restrict__ flow,
                    float* __restrict__ out) {
    extern __shared__ float sreg[];

    int bi = blockIdx.x;
    int tzi = bi % NTZ; bi /= NTZ;
    int txi = bi % NTX; bi /= NTX;
    int tyi = bi % NTY;
    int b   = bi / NTY;
    int ty0 = tyi * TY, tx0 = txi * TX, tz0 = tzi * TZ;
    int oy = ty0 - HLO, ox = tx0 - HLO, oz = tz0 - HLO;
    const float* imb = im + b * SB;

    int lane = threadIdx.x & 31;
    int w = threadIdx.x >> 5;

    // Phase 1: stage haloed region, one warp per (ry,rx) row (41 contiguous z).
    for (int row = w; row < NROWS; row += NWARP) {
        int ry = row / RX;           // constant divisor -> mul/shift
        int rx = row - ry * RX;
        int gy = oy + ry, gx = ox + rx;
        bool yx_ok = ((unsigned)gy < (unsigned)H_) && ((unsigned)gx < (unsigned)W_);
        const float* grow = imb + gy * SY + gx * SX + oz;
        float* srow = sreg + row * RZ;
#pragma unroll
        for (int zz = 0; zz < RZ; zz += 32) {
            int z = zz + lane;
            if (z < RZ) {
                int gz = oz + z;
                if (yx_ok && (unsigned)gz < (unsigned)D_)
                    srow[z] = __ldg(grow + z);
            }
        }
    }
    __syncthreads();

    // Phase 2: gather. Lane = z within tile (TZ == 32); warp per z-line.
#pragma unroll
    for (int it = 0; it < LINES / NWARP; ++it) {
        int l = it * NWARP + w;
        int tyv = l >> 3, txv = l & 7;  // TX == 8
        int gy = ty0 + tyv, gx = tx0 + txv, gz = tz0 + lane;
        int v = b * SB + gy * SY + gx * SX + gz;

        const float* fp = flow + (size_t)v * 3;
        float dyv = __ldg(fp + 0);  // flow[...,0] -> dy (H axis)
        float dxv = __ldg(fp + 1);  // flow[...,1] -> dx (W axis)
        float dzv = __ldg(fp + 2);  // flow[...,2] -> dz (D axis)

        float xf = dxv + (float)gx;
        float yf = dyv + (float)gy;
        float zf = dzv + (float)gz;

        // Reference-exact floor + clip
        int x0 = (int)floorf(xf);
        int y0 = (int)floorf(yf);
        int z0 = (int)floorf(zf);
        int x1 = min(max(x0 + 1, 0), W_ - 1);
        int y1 = min(max(y0 + 1, 0), H_ - 1);
        int z1 = min(max(z0 + 1, 0), D_ - 1);
        x0 = min(max(x0, 0), W_ - 1);
        y0 = min(max(y0, 0), H_ - 1);
        z0 = min(max(z0, 0), D_ - 1);

        float ddx = (float)x1 - xf;
        float ddy = (float)y1 - yf;
        float ddz = (float)z1 - zf;

        int x0r = x0 - ox, y0r = y0 - oy, z0r = z0 - oz;
        int x1r = x1 - ox, y1r = y1 - oy, z1r = z1 - oz;

        float res;
        if (((x0r | y0r | z0r) >= 0) & (x1r < RX) & (y1r < RY) & (z1r < RZ)) {
            int base = y0r * SXY + x0r * RZ + z0r;
            int dxo = (x1 - x0) * RZ;   // 0 or RZ
            int dyo = (y1 - y0) * SXY;  // 0 or SXY
            int dzo = z1 - z0;          // 0 or 1
            int b1 = base + dxo;
            int b2 = base + dyo;
            int b3 = b1 + dyo;
            float va = sreg[base],      ve = sreg[base + dzo];
            float vc = sreg[b1],        vg = sreg[b1 + dzo];
            float vb = sreg[b2],        vf = sreg[b2 + dzo];
            float vd = sreg[b3],        vh = sreg[b3 + dzo];
            res = wcomb(va, vb, vc, vd, ve, vf, vg, vh, ddx, ddy, ddz);
        } else {
            // Rare exact fallback: gather from global
            const float* p00 = imb + y0 * SY + x0 * SX;
            const float* p10 = imb + y1 * SY + x0 * SX;
            const float* p01 = imb + y0 * SY + x1 * SX;
            const float* p11 = imb + y1 * SY + x1 * SX;
            float va = __ldg(p00 + z0), vb = __ldg(p10 + z0);
            float vc = __ldg(p01 + z0), vd = __ldg(p11 + z0);
            float ve = __ldg(p00 + z1), vf = __ldg(p10 + z1);
            float vg = __ldg(p01 + z1), vh = __ldg(p11 + z1);
            res = wcomb(va, vb, vc, vd, ve, vf, vg, vh, ddx, ddy, ddz);
        }
        out[v] = res;
    }
}

extern "C" void kernel_launch(void* const* d_in, const int* in_sizes, int n_in,
                              void* d_out, int out_size) {
    const float* im = (const float*)d_in[0];    // image [4,160,160,160,1]
    const float* flow = (const float*)d_in[1];  // flow  [4,160,160,160,3]
    float* out = (float*)d_out;

    static bool attr_set = false;  // idempotent attribute opt-in (not a work guard)
    if (!attr_set) {
        cudaFuncSetAttribute(dense3d_tile_kernel,
                             cudaFuncAttributeMaxDynamicSharedMemorySize,
                             REG * (int)sizeof(float));
        attr_set = true;
    }
    dense3d_tile_kernel<<<NBLK, TPB, REG * sizeof(float)>>>(im, flow, out);
}